// round 15
// baseline (speedup 1.0000x reference)
#include <cuda_runtime.h>
#include <cuda_fp16.h>
#include <math.h>
#include <cstdint>

#define BB 64
#define CINN 64
#define COUTT 128
#define NPIX 1024
#define TC 4

// fused SMEM (per CTA, bytes): Ys fp16 [9 taps][33 rows][40 cols][4 co] = 95040
// (rows 0..31 data, 4-col zero halos; row 32 all-zero). W fp16 (40 x 144B) at 95040.
// red (128 f32) at 100800. Total 101312 -> 2 CTAs/SM.
#define ZROW 32
#define SM_W   95040
#define SM_RED 100800
#define SMEM_TOTAL 101376

// A_g: per (b,kstep=16cin) plane of 2048 uint4 in m16n8k16-fp16 A-fragment order.
__device__ uint4 A_g[BB * 4 * 2048];
__device__ float g_psum[COUTT * BB];
__device__ float g_psumsq[COUTT * BB];
__device__ float g_scale[COUTT];
__device__ float g_shift[COUTT];

__device__ __forceinline__ void mma_f16(float* d, const uint32_t* a, const uint32_t* b) {
    asm volatile("mma.sync.aligned.m16n8k16.row.col.f32.f16.f16.f32 "
        "{%0,%1,%2,%3}, {%4,%5,%6,%7}, {%8,%9}, {%0,%1,%2,%3};"
        : "+f"(d[0]), "+f"(d[1]), "+f"(d[2]), "+f"(d[3])
        : "r"(a[0]), "r"(a[1]), "r"(a[2]), "r"(a[3]), "r"(b[0]), "r"(b[1]));
}
__device__ __forceinline__ uint32_t pkh(float a, float b) {
    __half2 h = __floats2half2_rn(a, b);
    return *(uint32_t*)&h;
}
__device__ __forceinline__ int fd3(int a) { return (a + 24) / 3 - 8; }  // floor(a/3), a>=-24

// packed half2x2 helpers on uint2
__device__ __forceinline__ uint2 h4add(uint2 a, uint2 b) {
    uint2 r;
    __half2 ra = __hadd2(*(__half2*)&a.x, *(__half2*)&b.x);
    __half2 rb = __hadd2(*(__half2*)&a.y, *(__half2*)&b.y);
    r.x = *(uint32_t*)&ra; r.y = *(uint32_t*)&rb;
    return r;
}
__device__ __forceinline__ uint2 h4max(uint2 a, uint2 b) {
    uint2 r;
    __half2 ra = __hmax2(*(__half2*)&a.x, *(__half2*)&b.x);
    __half2 rb = __hmax2(*(__half2*)&a.y, *(__half2*)&b.y);
    r.x = *(uint32_t*)&ra; r.y = *(uint32_t*)&rb;
    return r;
}
__device__ __forceinline__ uint2 h4sel(bool c, uint2 b, uint2 a) {
    uint2 r; r.x = c ? b.x : a.x; r.y = c ? b.y : a.y; return r;
}
__device__ __forceinline__ float4 f4add(float4 a, float4 b) {
    float4 r;
    r.x = a.x + b.x; r.y = a.y + b.y; r.z = a.z + b.z; r.w = a.w + b.w;
    return r;
}

// ---- prologue: per (kstep=16cin, b) emit fp16 A plane in m16n8k16 fragment order ----
__global__ void __launch_bounds__(512) build_A(const float* __restrict__ x)
{
    extern __shared__ float Xs[];   // [16][1032]
    const int tid = threadIdx.x, ks = blockIdx.x, b = blockIdx.y;
    const float4* xg = (const float4*)(x + (size_t)b * CINN * NPIX + ks * 16 * NPIX);
#pragma unroll
    for (int j = 0; j < 8; j++) {
        int idx = tid + 512 * j;
        int ci = idx >> 8, px4 = idx & 255;
        *(float4*)(Xs + ci * 1032 + px4 * 4) = xg[idx];
    }
    __syncthreads();
    uint4* pb = A_g + (size_t)(b * 4 + ks) * 2048;
#pragma unroll
    for (int j = 0; j < 4; j++) {
        int idx = tid + 512 * j;
        int l = idx & 31, t = l & 3, g = l >> 2;
        int mtile = idx >> 5;
        int px = mtile * 16 + g;
        uint4 v;
        v.x = pkh(Xs[(2 * t) * 1032 + px],     Xs[(2 * t + 1) * 1032 + px]);
        v.y = pkh(Xs[(2 * t) * 1032 + px + 8], Xs[(2 * t + 1) * 1032 + px + 8]);
        v.z = pkh(Xs[(2 * t + 8) * 1032 + px],     Xs[(2 * t + 9) * 1032 + px]);
        v.w = pkh(Xs[(2 * t + 8) * 1032 + px + 8], Xs[(2 * t + 9) * 1032 + px + 8]);
        pb[idx] = v;
    }
}

__global__ void __launch_bounds__(512, 2)
fused_kernel(const int* __restrict__ hh, const int* __restrict__ wwp,
             const float* __restrict__ weight, const float* __restrict__ bias,
             float* __restrict__ out)
{
    extern __shared__ char smem[];
    uint2* Yh = (uint2*)smem;              // index: (tap*33+row)*40+col  (8B per entry)
    float* red = (float*)(smem + SM_RED);
    const int tid = threadIdx.x, wid = tid >> 5, l = tid & 31;
    const int b = blockIdx.y, co0 = blockIdx.x * TC;

    // zero column halos: 9 taps x 32 rows x 8 halo-cols (uint2 each) = 2304
    for (int i = tid; i < 2304; i += 512) {
        int tap = i >> 8, rem = i & 255, r = rem >> 3, k = rem & 7;
        int col = (k < 4) ? k : (k + 32);
        Yh[(tap * 33 + r) * 40 + col] = make_uint2(0u, 0u);
    }
    // zero row 32: 9 taps x 40 cols
    for (int i = tid; i < 360; i += 512) {
        int tap = i / 40, col = i - tap * 40;
        Yh[(tap * 33 + ZROW) * 40 + col] = make_uint2(0u, 0u);
    }
    // zero W pad rows 36..39 (36 words each)
    for (int i = tid; i < 144; i += 512)
        *(uint32_t*)(smem + SM_W + (36 + i / 36) * 144 + (i % 36) * 4) = 0u;
    // weights fp16: row n = tap*4+c, 144B stride (conflict-free B-frag LDS)
    for (int i = tid; i < TC * CINN * 9; i += 512) {
        int c = i / 576, r = i - c * 576, ci = r / 9, tap = r - ci * 9;
        float w = weight[(co0 + c) * 576 + ci * 9 + tap];
        *(__half*)(smem + SM_W + (tap * 4 + c) * 144 + ci * 2) = __float2half_rn(w);
    }
    __syncthreads();

    float acc[4][5][4];
#pragma unroll
    for (int mt = 0; mt < 4; mt++)
#pragma unroll
        for (int nt = 0; nt < 5; nt++)
#pragma unroll
            for (int k = 0; k < 4; k++) acc[mt][nt][k] = 0.f;

    const int lq = l & 3, ln = l >> 2;
    const int px0 = wid * 64;

#pragma unroll 1
    for (int ks = 0; ks < 4; ks++) {
        const uint4* pb = A_g + (size_t)(b * 4 + ks) * 2048;
        uint32_t bf[5][2];
#pragma unroll
        for (int nt = 0; nt < 5; nt++) {
            int base = SM_W + (nt * 8 + ln) * 144 + (ks * 16 + 2 * lq) * 2;
            bf[nt][0] = *(uint32_t*)(smem + base);
            bf[nt][1] = *(uint32_t*)(smem + base + 16);
        }
#pragma unroll
        for (int mt = 0; mt < 4; mt++) {
            uint4 a = pb[(wid * 4 + mt) * 32 + l];
#pragma unroll
            for (int nt = 0; nt < 5; nt++)
                mma_f16(acc[mt][nt], (const uint32_t*)&a, bf[nt]);
        }
    }
    __syncthreads();

    // readout: pack co-pairs to half2. c0 = nt*8+2lq -> tap=c0>>2, co=c0&3 (0 or 2)
#pragma unroll
    for (int mt = 0; mt < 4; mt++)
#pragma unroll
        for (int nt = 0; nt < 5; nt++) {
            int c0 = nt * 8 + 2 * lq;
            if (nt == 4 && lq >= 2) continue;  // c 36..39 unused
            int tap = c0 >> 2, co = c0 & 3;
            int px = px0 + mt * 16 + ln;
            int idx4 = (tap * 33 + (px >> 5)) * 40 + (px & 31) + 4;
            uint32_t p0 = pkh(acc[mt][nt][0], acc[mt][nt][1]);
            uint32_t p1 = pkh(acc[mt][nt][2], acc[mt][nt][3]);
            *(uint32_t*)((char*)Yh + idx4 * 8 + co * 2)       = p0;
            *(uint32_t*)((char*)Yh + (idx4 + 8) * 8 + co * 2) = p1;
        }
    __syncthreads();

    // ---- combine: packed half2x2 over 4 co, padded loads, factorized max ----
    int dh = 96 / hh[b];  if (dh < 1) dh = 1;
    int dw = 96 / wwp[b]; if (dw < 1) dw = 1;
    int rv[3][2]; bool rsel[3][3];
    int dcl0, dch0, dcl2, dch2; bool cdup0, cdup2, csel0[3], csel2[3];
#pragma unroll
    for (int k = 0; k < 3; k++) {
        int d0 = fd3((k - 1) * dh), d1 = fd3(1 + (k - 1) * dh), d2 = fd3(2 + (k - 1) * dh);
        rv[k][0] = d0; rv[k][1] = d2;
        rsel[k][0] = false; rsel[k][1] = (d1 != d0); rsel[k][2] = (d2 != d0);
    }
    {
        int c0 = fd3(-dw), c1 = fd3(1 - dw), c2 = fd3(2 - dw);
        dcl0 = c0; dch0 = c2; cdup0 = (c2 != c0);
        csel0[0] = false; csel0[1] = (c1 != c0); csel0[2] = (c2 != c0);
        int e0 = fd3(dw), e1 = fd3(1 + dw), e2 = fd3(2 + dw);
        dcl2 = e0; dch2 = e2; cdup2 = (e2 != e0);
        csel2[0] = false; csel2[1] = (e1 != e0); csel2[2] = (e2 != e0);
    }
    const bool vneed0 = (rv[0][1] != rv[0][0]);
    const bool vneed2 = (rv[2][1] != rv[2][0]);
    const float4 bias4 = *(const float4*)&bias[co0];
    float4 lsum4 = make_float4(0.f, 0.f, 0.f, 0.f);
    float4 lsq4  = make_float4(0.f, 0.f, 0.f, 0.f);
    const uint2 NEGINF = make_uint2(0xFC00FC00u, 0xFC00FC00u);

#pragma unroll
    for (int j = 0; j < 2; j++) {
        int pix = tid + (j << 9), py = pix >> 5, px = pix & 31;
        const int colA0 = 4 + px + dcl0, colB0 = 4 + px + dch0;
        const int colC  = 4 + px;
        const int colA2 = 4 + px + dcl2, colB2 = 4 + px + dch2;

        // center tap-row (ki=1): row offset 0, always valid (bias deferred)
        uint2 RS1[3];
        {
            int r3 = (3 * 33 + py) * 40, r4 = r3 + 1320, r5 = r4 + 1320;
            uint2 A0 = Yh[r3 + colA0];
            uint2 B0 = cdup0 ? Yh[r3 + colB0] : A0;
            uint2 Lc = Yh[r4 + colC];
            uint2 A2 = Yh[r5 + colA2];
            uint2 B2 = cdup2 ? Yh[r5 + colB2] : A2;
#pragma unroll
            for (int s = 0; s < 3; s++)
                RS1[s] = h4add(Lc, h4add(h4sel(csel0[s], B0, A0), h4sel(csel2[s], B2, A2)));
        }
        uint2 RS0[2][3], RS2[2][3];
#pragma unroll
        for (int ki = 0; ki < 3; ki += 2) {
            uint2 (*RS)[3] = (ki == 0) ? RS0 : RS2;
            const bool vneed = (ki == 0) ? vneed0 : vneed2;
#pragma unroll
            for (int v = 0; v < 2; v++) {
                if (v == 1 && !vneed) {
#pragma unroll
                    for (int s = 0; s < 3; s++) RS[1][s] = RS[0][s];
                    break;
                }
                int row = py + rv[ki][v];
                int rowsel = ((unsigned)row < 32u) ? row : ZROW;
                int t0 = ((ki * 3) * 33 + rowsel) * 40, t1 = t0 + 1320, t2 = t1 + 1320;
                uint2 A0 = Yh[t0 + colA0];
                uint2 B0 = cdup0 ? Yh[t0 + colB0] : A0;
                uint2 Lc = Yh[t1 + colC];
                uint2 A2 = Yh[t2 + colA2];
                uint2 B2 = cdup2 ? Yh[t2 + colB2] : A2;
#pragma unroll
                for (int s = 0; s < 3; s++)
                    RS[v][s] = h4add(Lc, h4add(h4sel(csel0[s], B0, A0), h4sel(csel2[s], B2, A2)));
            }
        }
        // mall = max_s( RS1[s] + max_r(v0[r][s]+v2[r][s]) ); mx = bias + mall (fp32)
        uint2 mall = NEGINF;
#pragma unroll
        for (int s = 0; s < 3; s++) {
            uint2 t0 = h4add(RS0[0][s], RS2[0][s]);
            uint2 t1 = h4add(h4sel(rsel[0][1], RS0[1][s], RS0[0][s]),
                             h4sel(rsel[2][1], RS2[1][s], RS2[0][s]));
            uint2 t2 = h4add(h4sel(rsel[0][2], RS0[1][s], RS0[0][s]),
                             h4sel(rsel[2][2], RS2[1][s], RS2[0][s]));
            uint2 u = h4max(t0, h4max(t1, t2));
            mall = h4max(mall, h4add(u, RS1[s]));
        }
        float2 f01 = __half22float2(*(__half2*)&mall.x);
        float2 f23 = __half22float2(*(__half2*)&mall.y);
        float4 mx = make_float4(bias4.x + f01.x, bias4.y + f01.y,
                                bias4.z + f23.x, bias4.w + f23.y);
        float* ob = out + ((size_t)b * COUTT + co0) * NPIX + pix;
        ob[0]        = mx.x;
        ob[NPIX]     = mx.y;
        ob[2 * NPIX] = mx.z;
        ob[3 * NPIX] = mx.w;
        lsum4 = f4add(lsum4, mx);
        lsq4.x += mx.x * mx.x; lsq4.y += mx.y * mx.y;
        lsq4.z += mx.z * mx.z; lsq4.w += mx.w * mx.w;
    }
#pragma unroll
    for (int o = 16; o > 0; o >>= 1) {
        lsum4.x += __shfl_xor_sync(0xFFFFFFFFu, lsum4.x, o);
        lsum4.y += __shfl_xor_sync(0xFFFFFFFFu, lsum4.y, o);
        lsum4.z += __shfl_xor_sync(0xFFFFFFFFu, lsum4.z, o);
        lsum4.w += __shfl_xor_sync(0xFFFFFFFFu, lsum4.w, o);
        lsq4.x  += __shfl_xor_sync(0xFFFFFFFFu, lsq4.x, o);
        lsq4.y  += __shfl_xor_sync(0xFFFFFFFFu, lsq4.y, o);
        lsq4.z  += __shfl_xor_sync(0xFFFFFFFFu, lsq4.z, o);
        lsq4.w  += __shfl_xor_sync(0xFFFFFFFFu, lsq4.w, o);
    }
    __syncthreads();
    if (l == 0) {
        float* rw = red + wid * 8;
        rw[0] = lsum4.x; rw[1] = lsq4.x;
        rw[2] = lsum4.y; rw[3] = lsq4.y;
        rw[4] = lsum4.z; rw[5] = lsq4.z;
        rw[6] = lsum4.w; rw[7] = lsq4.w;
    }
    __syncthreads();
    if (tid < TC) {
        float s = 0.f, q = 0.f;
#pragma unroll
        for (int wdx = 0; wdx < 16; wdx++) {
            s += red[wdx * 8 + tid * 2];
            q += red[wdx * 8 + tid * 2 + 1];
        }
        g_psum[(co0 + tid) * BB + b] = s;
        g_psumsq[(co0 + tid) * BB + b] = q;
    }
}

// warp-per-channel: grid 4 x 1024 threads = 128 warps
__global__ void __launch_bounds__(1024)
stats_kernel(const float* __restrict__ gamma, const float* __restrict__ beta)
{
    int gw = (blockIdx.x * 1024 + threadIdx.x) >> 5;   // channel 0..127
    int l = threadIdx.x & 31;
    float s = g_psum[gw * BB + l] + g_psum[gw * BB + 32 + l];
    float q = g_psumsq[gw * BB + l] + g_psumsq[gw * BB + 32 + l];
#pragma unroll
    for (int o = 16; o > 0; o >>= 1) {
        s += __shfl_xor_sync(0xFFFFFFFFu, s, o);
        q += __shfl_xor_sync(0xFFFFFFFFu, q, o);
    }
    if (l == 0) {
        const float inv = 1.0f / 65536.0f;
        float mean = s * inv, var = q * inv - mean * mean;
        float sc = gamma[gw] * rsqrtf(var + 1e-5f);
        g_scale[gw] = sc;
        g_shift[gw] = beta[gw] - mean * sc;
    }
}

// 1024 blocks x 1024 threads, 2 independent float4 per thread
__global__ void __launch_bounds__(1024)
apply_kernel(float* __restrict__ out)
{
    int t = blockIdx.x * 1024 + threadIdx.x;   // 0..1048575
    float4* o = (float4*)out;
#pragma unroll
    for (int j = 0; j < 2; j++) {
        int i = t + j * 1048576;
        int c = (i >> 8) & 127;
        float4 v = o[i];
        float sc = g_scale[c], sh = g_shift[c];
        v.x = fmaxf(fmaf(v.x, sc, sh), 0.f);
        v.y = fmaxf(fmaf(v.y, sc, sh), 0.f);
        v.z = fmaxf(fmaf(v.z, sc, sh), 0.f);
        v.w = fmaxf(fmaf(v.w, sc, sh), 0.f);
        o[i] = v;
    }
}

extern "C" void kernel_launch(void* const* d_in, const int* in_sizes, int n_in,
                              void* d_out, int out_size)
{
    const float* x      = (const float*)d_in[0];
    const int*   h      = (const int*)  d_in[1];
    const int*   w      = (const int*)  d_in[2];
    const float* weight = (const float*)d_in[3];
    const float* bias   = (const float*)d_in[4];
    const float* gamma  = (const float*)d_in[5];
    const float* beta   = (const float*)d_in[6];
    float* out = (float*)d_out;

    cudaFuncSetAttribute(build_A, cudaFuncAttributeMaxDynamicSharedMemorySize, 66048);
    cudaFuncSetAttribute(fused_kernel, cudaFuncAttributeMaxDynamicSharedMemorySize, SMEM_TOTAL);

    build_A<<<dim3(4, BB), 512, 66048>>>(x);
    fused_kernel<<<dim3(COUTT / TC, BB), 512, SMEM_TOTAL>>>(h, w, weight, bias, out);
    stats_kernel<<<4, 1024>>>(gamma, beta);
    apply_kernel<<<1024, 1024>>>(out);
}

// round 16
// speedup vs baseline: 1.8908x; 1.8908x over previous
#include <cuda_runtime.h>
#include <cuda_fp16.h>
#include <math.h>
#include <cstdint>

#define BB 64
#define CINN 64
#define COUTT 128
#define NPIX 1024
#define TC 4

// fused SMEM: Ys[9 taps][33 rows][40 cols][4 co] f32 = 190080 B (rows 0..31 data, 4-col zero
// halos; row 32 all-zero). Wf frag-order (640 uint2) at 190080. red (136 f32) at 195200.
#define ZROW 32
#define SM_W   190080
#define SM_RED 195200
#define SMEM_TOTAL 195776

// A_g: per (b,kstep=16cin) plane of 2048 uint4 in m16n8k16-fp16 A-fragment order.
__device__ uint4 A_g[BB * 4 * 2048];
__device__ float g_psum[COUTT * BB];
__device__ float g_psumsq[COUTT * BB];
__device__ float g_scale[COUTT];
__device__ float g_shift[COUTT];
__device__ int   g_cnt;

__device__ __forceinline__ void mma_f16(float* d, const uint32_t* a, const uint32_t* b) {
    asm volatile("mma.sync.aligned.m16n8k16.row.col.f32.f16.f16.f32 "
        "{%0,%1,%2,%3}, {%4,%5,%6,%7}, {%8,%9}, {%0,%1,%2,%3};"
        : "+f"(d[0]), "+f"(d[1]), "+f"(d[2]), "+f"(d[3])
        : "r"(a[0]), "r"(a[1]), "r"(a[2]), "r"(a[3]), "r"(b[0]), "r"(b[1]));
}
__device__ __forceinline__ uint32_t pkh(float a, float b) {
    __half2 h = __floats2half2_rn(a, b);
    return *(uint32_t*)&h;
}
__device__ __forceinline__ int fd3(int a) { return (a + 24) / 3 - 8; }  // floor(a/3), a>=-24

__device__ __forceinline__ float4 f4sel(bool c, float4 b, float4 a) {
    float4 r;
    r.x = c ? b.x : a.x; r.y = c ? b.y : a.y; r.z = c ? b.z : a.z; r.w = c ? b.w : a.w;
    return r;
}
__device__ __forceinline__ float4 f4add(float4 a, float4 b) {
    float4 r;
    r.x = a.x + b.x; r.y = a.y + b.y; r.z = a.z + b.z; r.w = a.w + b.w;
    return r;
}
__device__ __forceinline__ float4 f4max(float4 a, float4 b) {
    float4 r;
    r.x = fmaxf(a.x, b.x); r.y = fmaxf(a.y, b.y); r.z = fmaxf(a.z, b.z); r.w = fmaxf(a.w, b.w);
    return r;
}

// ---- prologue: per (kstep=16cin, b) emit fp16 A plane in m16n8k16 fragment order ----
__global__ void __launch_bounds__(512) build_A(const float* __restrict__ x)
{
    extern __shared__ float Xs[];   // [16][1032]
    const int tid = threadIdx.x, ks = blockIdx.x, b = blockIdx.y;
    if (ks == 0 && b == 0 && tid == 0) g_cnt = 0;   // reset stats counter each replay
    const float4* xg = (const float4*)(x + (size_t)b * CINN * NPIX + ks * 16 * NPIX);
#pragma unroll
    for (int j = 0; j < 8; j++) {
        int idx = tid + 512 * j;
        int ci = idx >> 8, px4 = idx & 255;
        *(float4*)(Xs + ci * 1032 + px4 * 4) = xg[idx];
    }
    __syncthreads();
    uint4* pb = A_g + (size_t)(b * 4 + ks) * 2048;
#pragma unroll
    for (int j = 0; j < 4; j++) {
        int idx = tid + 512 * j;
        int l = idx & 31, t = l & 3, g = l >> 2;
        int mtile = idx >> 5;
        int px = mtile * 16 + g;
        uint4 v;
        v.x = pkh(Xs[(2 * t) * 1032 + px],     Xs[(2 * t + 1) * 1032 + px]);
        v.y = pkh(Xs[(2 * t) * 1032 + px + 8], Xs[(2 * t + 1) * 1032 + px + 8]);
        v.z = pkh(Xs[(2 * t + 8) * 1032 + px],     Xs[(2 * t + 9) * 1032 + px]);
        v.w = pkh(Xs[(2 * t + 8) * 1032 + px + 8], Xs[(2 * t + 9) * 1032 + px + 8]);
        pb[idx] = v;
    }
}

__global__ void __launch_bounds__(512, 1)
fused_kernel(const int* __restrict__ hh, const int* __restrict__ wwp,
             const float* __restrict__ weight, const float* __restrict__ bias,
             const float* __restrict__ gamma, const float* __restrict__ beta,
             float* __restrict__ out)
{
    extern __shared__ char smem[];
    float* Y = (float*)smem;
    float4* Y4 = (float4*)smem;
    uint2* Wf = (uint2*)(smem + SM_W);
    float* red = (float*)(smem + SM_RED);
    const int tid = threadIdx.x, wid = tid >> 5, l = tid & 31;
    const int b = blockIdx.y, co0 = blockIdx.x * TC;

    // zero column halos: 9 taps x 32 rows x 8 halo-cols x 4 co = 9216 words
    for (int i = tid; i < 9216; i += 512) {
        int tap = i >> 10, rem = i & 1023, r = rem >> 5, k = (rem >> 2) & 7, co = i & 3;
        int col = (k < 4) ? k : (k + 32);
        Y[((tap * 33 + r) * 40 + col) * 4 + co] = 0.f;
    }
    // zero row 32: 9 taps x 160 words
    for (int i = tid; i < 1440; i += 512) {
        int tap = i / 160, rem = i - tap * 160;
        Y[(tap * 33 + ZROW) * 160 + rem] = 0.f;
    }
    // W in b-fragment order: Wf[(ks*5+nt)*32 + lane] = {pk(k0,k0+1), pk(k0+8,k0+9)},
    // n = nt*8 + lane>>2 (tap=n>>2, c=n&3), k0 = ks*16 + 2*(lane&3). n>=36 -> 0.
    for (int i = tid; i < 640; i += 512) {
        int lane = i & 31, nt = (i >> 5) % 5, ks = i / 160;
        int n = nt * 8 + (lane >> 2);
        uint2 e = make_uint2(0u, 0u);
        if (n < 36) {
            const float* wp = weight + (co0 + (n & 3)) * 576 + (n >> 2);
            int k0 = ks * 16 + 2 * (lane & 3);
            e.x = pkh(wp[k0 * 9], wp[(k0 + 1) * 9]);
            e.y = pkh(wp[(k0 + 8) * 9], wp[(k0 + 9) * 9]);
        }
        Wf[i] = e;
    }
    __syncthreads();

    float acc[4][5][4];
#pragma unroll
    for (int mt = 0; mt < 4; mt++)
#pragma unroll
        for (int nt = 0; nt < 5; nt++)
#pragma unroll
            for (int k = 0; k < 4; k++) acc[mt][nt][k] = 0.f;

    const int lq = l & 3, ln = l >> 2;
    const int px0 = wid * 64;

#pragma unroll 1
    for (int ks = 0; ks < 4; ks++) {
        const uint4* pb = A_g + (size_t)(b * 4 + ks) * 2048;
        uint2 bf[5];
#pragma unroll
        for (int nt = 0; nt < 5; nt++) bf[nt] = Wf[(ks * 5 + nt) * 32 + l];
#pragma unroll
        for (int mt = 0; mt < 4; mt++) {
            uint4 a = pb[(wid * 4 + mt) * 32 + l];
#pragma unroll
            for (int nt = 0; nt < 5; nt++)
                mma_f16(acc[mt][nt], (const uint32_t*)&a, (const uint32_t*)&bf[nt]);
        }
    }
    __syncthreads();

    // readout into [tap][row][col][co]: c-row n = tap*4+co
#pragma unroll
    for (int mt = 0; mt < 4; mt++)
#pragma unroll
        for (int nt = 0; nt < 5; nt++) {
            int c0 = nt * 8 + 2 * lq;
            if (nt == 4 && lq >= 2) continue;  // c 36..39 unused
            int tap = c0 >> 2, co = c0 & 3;
            int px = px0 + mt * 16 + ln;
            int base = ((tap * 33 + (px >> 5)) * 40 + (px & 31) + 4) * 4 + co;
            Y[base]      = acc[mt][nt][0];
            Y[base + 1]  = acc[mt][nt][1];
            Y[base + 32] = acc[mt][nt][2];  // col +8
            Y[base + 33] = acc[mt][nt][3];
        }
    __syncthreads();

    // ---- combine: float4 over 4 co, padded loads, factorized max, deferred bias ----
    int dh = 96 / hh[b];  if (dh < 1) dh = 1;
    int dw = 96 / wwp[b]; if (dw < 1) dw = 1;
    int rv[3][2]; bool rsel[3][3];
    int dcl0, dch0, dcl2, dch2; bool cdup0, cdup2, csel0[3], csel2[3];
#pragma unroll
    for (int k = 0; k < 3; k++) {
        int d0 = fd3((k - 1) * dh), d1 = fd3(1 + (k - 1) * dh), d2 = fd3(2 + (k - 1) * dh);
        rv[k][0] = d0; rv[k][1] = d2;
        rsel[k][0] = false; rsel[k][1] = (d1 != d0); rsel[k][2] = (d2 != d0);
    }
    {
        int c0 = fd3(-dw), c1 = fd3(1 - dw), c2 = fd3(2 - dw);
        dcl0 = c0; dch0 = c2; cdup0 = (c2 != c0);
        csel0[0] = false; csel0[1] = (c1 != c0); csel0[2] = (c2 != c0);
        int e0 = fd3(dw), e1 = fd3(1 + dw), e2 = fd3(2 + dw);
        dcl2 = e0; dch2 = e2; cdup2 = (e2 != e0);
        csel2[0] = false; csel2[1] = (e1 != e0); csel2[2] = (e2 != e0);
    }
    const bool vneed0 = (rv[0][1] != rv[0][0]);
    const bool vneed2 = (rv[2][1] != rv[2][0]);
    const float4 bias4 = *(const float4*)&bias[co0];
    float4 lsum4 = make_float4(0.f, 0.f, 0.f, 0.f);
    float4 lsq4  = make_float4(0.f, 0.f, 0.f, 0.f);

#pragma unroll
    for (int j = 0; j < 2; j++) {
        int pix = tid + (j << 9), py = pix >> 5, px = pix & 31;
        const int colA0 = 4 + px + dcl0, colB0 = 4 + px + dch0;
        const int colC  = 4 + px;
        const int colA2 = 4 + px + dcl2, colB2 = 4 + px + dch2;

        float4 RS1[3];
        {
            int r3 = (3 * 33 + py) * 40, r4 = r3 + 1320, r5 = r4 + 1320;
            float4 A0 = Y4[r3 + colA0];
            float4 B0 = cdup0 ? Y4[r3 + colB0] : A0;
            float4 Lc = Y4[r4 + colC];
            float4 A2 = Y4[r5 + colA2];
            float4 B2 = cdup2 ? Y4[r5 + colB2] : A2;
#pragma unroll
            for (int s = 0; s < 3; s++)
                RS1[s] = f4add(Lc,
                          f4add(f4sel(csel0[s], B0, A0), f4sel(csel2[s], B2, A2)));
        }
        float4 RS0[2][3], RS2[2][3];
#pragma unroll
        for (int ki = 0; ki < 3; ki += 2) {
            float4 (*RS)[3] = (ki == 0) ? RS0 : RS2;
            const bool vneed = (ki == 0) ? vneed0 : vneed2;
#pragma unroll
            for (int v = 0; v < 2; v++) {
                if (v == 1 && !vneed) {
#pragma unroll
                    for (int s = 0; s < 3; s++) RS[1][s] = RS[0][s];
                    break;
                }
                int row = py + rv[ki][v];
                int rowsel = ((unsigned)row < 32u) ? row : ZROW;
                int t0 = ((ki * 3) * 33 + rowsel) * 40, t1 = t0 + 1320, t2 = t1 + 1320;
                float4 A0 = Y4[t0 + colA0];
                float4 B0 = cdup0 ? Y4[t0 + colB0] : A0;
                float4 Lc = Y4[t1 + colC];
                float4 A2 = Y4[t2 + colA2];
                float4 B2 = cdup2 ? Y4[t2 + colB2] : A2;
#pragma unroll
                for (int s = 0; s < 3; s++)
                    RS[v][s] = f4add(Lc,
                        f4add(f4sel(csel0[s], B0, A0), f4sel(csel2[s], B2, A2)));
            }
        }
        float4 mall = make_float4(-INFINITY, -INFINITY, -INFINITY, -INFINITY);
#pragma unroll
        for (int s = 0; s < 3; s++) {
            float4 t0 = f4add(RS0[0][s], RS2[0][s]);
            float4 t1 = f4add(rsel[0][1] ? RS0[1][s] : RS0[0][s],
                              rsel[2][1] ? RS2[1][s] : RS2[0][s]);
            float4 t2 = f4add(rsel[0][2] ? RS0[1][s] : RS0[0][s],
                              rsel[2][2] ? RS2[1][s] : RS2[0][s]);
            float4 u = f4max(t0, f4max(t1, t2));
            mall = f4max(mall, f4add(u, RS1[s]));
        }
        float4 mx = f4add(bias4, mall);
        float* ob = out + ((size_t)b * COUTT + co0) * NPIX + pix;
        ob[0]        = mx.x;
        ob[NPIX]     = mx.y;
        ob[2 * NPIX] = mx.z;
        ob[3 * NPIX] = mx.w;
        lsum4 = f4add(lsum4, mx);
        lsq4.x += mx.x * mx.x; lsq4.y += mx.y * mx.y;
        lsq4.z += mx.z * mx.z; lsq4.w += mx.w * mx.w;
    }
#pragma unroll
    for (int o = 16; o > 0; o >>= 1) {
        lsum4.x += __shfl_xor_sync(0xFFFFFFFFu, lsum4.x, o);
        lsum4.y += __shfl_xor_sync(0xFFFFFFFFu, lsum4.y, o);
        lsum4.z += __shfl_xor_sync(0xFFFFFFFFu, lsum4.z, o);
        lsum4.w += __shfl_xor_sync(0xFFFFFFFFu, lsum4.w, o);
        lsq4.x  += __shfl_xor_sync(0xFFFFFFFFu, lsq4.x, o);
        lsq4.y  += __shfl_xor_sync(0xFFFFFFFFu, lsq4.y, o);
        lsq4.z  += __shfl_xor_sync(0xFFFFFFFFu, lsq4.z, o);
        lsq4.w  += __shfl_xor_sync(0xFFFFFFFFu, lsq4.w, o);
    }
    __syncthreads();
    if (l == 0) {
        float* rw = red + wid * 8;
        rw[0] = lsum4.x; rw[1] = lsq4.x;
        rw[2] = lsum4.y; rw[3] = lsq4.y;
        rw[4] = lsum4.z; rw[5] = lsq4.z;
        rw[6] = lsum4.w; rw[7] = lsq4.w;
    }
    __syncthreads();
    if (tid < TC) {
        float s = 0.f, q = 0.f;
#pragma unroll
        for (int wdx = 0; wdx < 16; wdx++) {
            s += red[wdx * 8 + tid * 2];
            q += red[wdx * 8 + tid * 2 + 1];
        }
        g_psum[(co0 + tid) * BB + b] = s;
        g_psumsq[(co0 + tid) * BB + b] = q;
    }
    // ---- last CTA computes BN scale/shift (threadfence-reduction pattern) ----
    __threadfence();
    __syncthreads();
    if (tid == 0) {
        int old = atomicAdd(&g_cnt, 1);
        ((int*)red)[128] = (old == 2047) ? 1 : 0;
    }
    __syncthreads();
    if (((int*)red)[128]) {
        __threadfence();
        for (int c = tid; c < COUTT; c += 512) {
            float s = 0.f, q = 0.f;
#pragma unroll 8
            for (int i = 0; i < BB; i++) { s += g_psum[c * BB + i]; q += g_psumsq[c * BB + i]; }
            const float inv = 1.0f / 65536.0f;
            float mean = s * inv, var = q * inv - mean * mean;
            float sc = gamma[c] * rsqrtf(var + 1e-5f);
            g_scale[c] = sc;
            g_shift[c] = beta[c] - mean * sc;
        }
    }
}

__global__ void __launch_bounds__(1024)
apply_kernel(float* __restrict__ out)
{
    int i = blockIdx.x * 1024 + threadIdx.x;   // grid 2048, one float4 per thread
    int c = (i >> 8) & 127;
    float4 v = ((float4*)out)[i];
    float sc = g_scale[c], sh = g_shift[c];
    v.x = fmaxf(fmaf(v.x, sc, sh), 0.f);
    v.y = fmaxf(fmaf(v.y, sc, sh), 0.f);
    v.z = fmaxf(fmaf(v.z, sc, sh), 0.f);
    v.w = fmaxf(fmaf(v.w, sc, sh), 0.f);
    ((float4*)out)[i] = v;
}

extern "C" void kernel_launch(void* const* d_in, const int* in_sizes, int n_in,
                              void* d_out, int out_size)
{
    const float* x      = (const float*)d_in[0];
    const int*   h      = (const int*)  d_in[1];
    const int*   w      = (const int*)  d_in[2];
    const float* weight = (const float*)d_in[3];
    const float* bias   = (const float*)d_in[4];
    const float* gamma  = (const float*)d_in[5];
    const float* beta   = (const float*)d_in[6];
    float* out = (float*)d_out;

    cudaFuncSetAttribute(build_A, cudaFuncAttributeMaxDynamicSharedMemorySize, 66048);
    cudaFuncSetAttribute(fused_kernel, cudaFuncAttributeMaxDynamicSharedMemorySize, SMEM_TOTAL);

    build_A<<<dim3(4, BB), 512, 66048>>>(x);
    fused_kernel<<<dim3(COUTT / TC, BB), 512, SMEM_TOTAL>>>(h, w, weight, bias, gamma, beta, out);
    apply_kernel<<<2048, 1024>>>(out);
}

// round 17
// speedup vs baseline: 2.2178x; 1.1730x over previous
#include <cuda_runtime.h>
#include <cuda_fp16.h>
#include <math.h>
#include <cstdint>

#define BB 64
#define CINN 64
#define COUTT 128
#define NPIX 1024
#define TC 4

// fused SMEM: Ys[9 taps][33 rows][40 cols][4 co] f32 = 190080 B (rows 0..31 data, 4-col zero
// halos; row 32 all-zero). Wf frag-order (640 uint2 = 5120 B) at 190080. red at 195200.
#define ZROW 32
#define SM_W   190080
#define SM_RED 195200
#define SMEM_TOTAL 195712

// A_g: per (b,kstep=16cin) plane of 2048 uint4 in m16n8k16-fp16 A-fragment order.
__device__ uint4 A_g[BB * 4 * 2048];
__device__ float g_psum[COUTT * BB];
__device__ float g_psumsq[COUTT * BB];
__device__ float g_scale[COUTT];
__device__ float g_shift[COUTT];

__device__ __forceinline__ void mma_f16(float* d, const uint32_t* a, const uint32_t* b) {
    asm volatile("mma.sync.aligned.m16n8k16.row.col.f32.f16.f16.f32 "
        "{%0,%1,%2,%3}, {%4,%5,%6,%7}, {%8,%9}, {%0,%1,%2,%3};"
        : "+f"(d[0]), "+f"(d[1]), "+f"(d[2]), "+f"(d[3])
        : "r"(a[0]), "r"(a[1]), "r"(a[2]), "r"(a[3]), "r"(b[0]), "r"(b[1]));
}
__device__ __forceinline__ uint32_t pkh(float a, float b) {
    __half2 h = __floats2half2_rn(a, b);
    return *(uint32_t*)&h;
}
__device__ __forceinline__ int fd3(int a) { return (a + 24) / 3 - 8; }  // floor(a/3), a>=-24

__device__ __forceinline__ float4 f4sel(bool c, float4 b, float4 a) {
    float4 r;
    r.x = c ? b.x : a.x; r.y = c ? b.y : a.y; r.z = c ? b.z : a.z; r.w = c ? b.w : a.w;
    return r;
}
__device__ __forceinline__ float4 f4add(float4 a, float4 b) {
    float4 r;
    r.x = a.x + b.x; r.y = a.y + b.y; r.z = a.z + b.z; r.w = a.w + b.w;
    return r;
}
__device__ __forceinline__ float4 f4max(float4 a, float4 b) {
    float4 r;
    r.x = fmaxf(a.x, b.x); r.y = fmaxf(a.y, b.y); r.z = fmaxf(a.z, b.z); r.w = fmaxf(a.w, b.w);
    return r;
}

// ---- prologue: per (kstep=16cin, b) emit fp16 A plane in m16n8k16 fragment order ----
__global__ void __launch_bounds__(512) build_A(const float* __restrict__ x)
{
    extern __shared__ float Xs[];   // [16][1032]
    const int tid = threadIdx.x, ks = blockIdx.x, b = blockIdx.y;
    const float4* xg = (const float4*)(x + (size_t)b * CINN * NPIX + ks * 16 * NPIX);
#pragma unroll
    for (int j = 0; j < 8; j++) {
        int idx = tid + 512 * j;
        int ci = idx >> 8, px4 = idx & 255;
        *(float4*)(Xs + ci * 1032 + px4 * 4) = xg[idx];
    }
    __syncthreads();
    uint4* pb = A_g + (size_t)(b * 4 + ks) * 2048;
#pragma unroll
    for (int j = 0; j < 4; j++) {
        int idx = tid + 512 * j;
        int l = idx & 31, t = l & 3, g = l >> 2;
        int mtile = idx >> 5;
        int px = mtile * 16 + g;
        uint4 v;
        v.x = pkh(Xs[(2 * t) * 1032 + px],     Xs[(2 * t + 1) * 1032 + px]);
        v.y = pkh(Xs[(2 * t) * 1032 + px + 8], Xs[(2 * t + 1) * 1032 + px + 8]);
        v.z = pkh(Xs[(2 * t + 8) * 1032 + px],     Xs[(2 * t + 9) * 1032 + px]);
        v.w = pkh(Xs[(2 * t + 8) * 1032 + px + 8], Xs[(2 * t + 9) * 1032 + px + 8]);
        pb[idx] = v;
    }
}

__global__ void __launch_bounds__(512, 1)
fused_kernel(const int* __restrict__ hh, const int* __restrict__ wwp,
             const float* __restrict__ weight, const float* __restrict__ bias,
             float* __restrict__ out)
{
    extern __shared__ char smem[];
    float* Y = (float*)smem;
    float4* Y4 = (float4*)smem;
    uint2* Wf = (uint2*)(smem + SM_W);
    float* red = (float*)(smem + SM_RED);
    const int tid = threadIdx.x, wid = tid >> 5, l = tid & 31;
    const int b = blockIdx.y, co0 = blockIdx.x * TC;

    // zero column halos: 9 taps x 32 rows x 8 halo-cols x 4 co = 9216 words
    for (int i = tid; i < 9216; i += 512) {
        int tap = i >> 10, rem = i & 1023, r = rem >> 5, k = (rem >> 2) & 7, co = i & 3;
        int col = (k < 4) ? k : (k + 32);
        Y[((tap * 33 + r) * 40 + col) * 4 + co] = 0.f;
    }
    // zero row 32: 9 taps x 160 words
    for (int i = tid; i < 1440; i += 512) {
        int tap = i / 160, rem = i - tap * 160;
        Y[(tap * 33 + ZROW) * 160 + rem] = 0.f;
    }
    // W in b-fragment order: Wf[(ks*5+nt)*32 + lane] = {pk(k0,k0+1), pk(k0+8,k0+9)},
    // n = nt*8 + lane>>2 (tap=n>>2, c=n&3), k0 = ks*16 + 2*(lane&3). n>=36 -> 0.
    for (int i = tid; i < 640; i += 512) {
        int lane = i & 31, nt = (i >> 5) % 5, ks = i / 160;
        int n = nt * 8 + (lane >> 2);
        uint2 e = make_uint2(0u, 0u);
        if (n < 36) {
            const float* wp = weight + (co0 + (n & 3)) * 576 + (n >> 2);
            int k0 = ks * 16 + 2 * (lane & 3);
            e.x = pkh(wp[k0 * 9], wp[(k0 + 1) * 9]);
            e.y = pkh(wp[(k0 + 8) * 9], wp[(k0 + 9) * 9]);
        }
        Wf[i] = e;
    }
    __syncthreads();

    float acc[4][5][4];
#pragma unroll
    for (int mt = 0; mt < 4; mt++)
#pragma unroll
        for (int nt = 0; nt < 5; nt++)
#pragma unroll
            for (int k = 0; k < 4; k++) acc[mt][nt][k] = 0.f;

    const int lq = l & 3, ln = l >> 2;
    const int px0 = wid * 64;

#pragma unroll 1
    for (int ks = 0; ks < 4; ks++) {
        const uint4* pb = A_g + (size_t)(b * 4 + ks) * 2048;
        uint2 bf[5];
#pragma unroll
        for (int nt = 0; nt < 5; nt++) bf[nt] = Wf[(ks * 5 + nt) * 32 + l];
#pragma unroll
        for (int mt = 0; mt < 4; mt++) {
            uint4 a = pb[(wid * 4 + mt) * 32 + l];
#pragma unroll
            for (int nt = 0; nt < 5; nt++)
                mma_f16(acc[mt][nt], (const uint32_t*)&a, (const uint32_t*)&bf[nt]);
        }
    }
    __syncthreads();

    // readout into [tap][row][col][co]: c-row n = tap*4+co
#pragma unroll
    for (int mt = 0; mt < 4; mt++)
#pragma unroll
        for (int nt = 0; nt < 5; nt++) {
            int c0 = nt * 8 + 2 * lq;
            if (nt == 4 && lq >= 2) continue;  // c 36..39 unused
            int tap = c0 >> 2, co = c0 & 3;
            int px = px0 + mt * 16 + ln;
            int base = ((tap * 33 + (px >> 5)) * 40 + (px & 31) + 4) * 4 + co;
            Y[base]      = acc[mt][nt][0];
            Y[base + 1]  = acc[mt][nt][1];
            Y[base + 32] = acc[mt][nt][2];  // col +8
            Y[base + 33] = acc[mt][nt][3];
        }
    __syncthreads();

    // ---- combine: float4 over 4 co, padded loads, factorized max, deferred bias ----
    int dh = 96 / hh[b];  if (dh < 1) dh = 1;
    int dw = 96 / wwp[b]; if (dw < 1) dw = 1;
    int rv[3][2]; bool rsel[3][3];
    int dcl0, dch0, dcl2, dch2; bool cdup0, cdup2, csel0[3], csel2[3];
#pragma unroll
    for (int k = 0; k < 3; k++) {
        int d0 = fd3((k - 1) * dh), d1 = fd3(1 + (k - 1) * dh), d2 = fd3(2 + (k - 1) * dh);
        rv[k][0] = d0; rv[k][1] = d2;
        rsel[k][0] = false; rsel[k][1] = (d1 != d0); rsel[k][2] = (d2 != d0);
    }
    {
        int c0 = fd3(-dw), c1 = fd3(1 - dw), c2 = fd3(2 - dw);
        dcl0 = c0; dch0 = c2; cdup0 = (c2 != c0);
        csel0[0] = false; csel0[1] = (c1 != c0); csel0[2] = (c2 != c0);
        int e0 = fd3(dw), e1 = fd3(1 + dw), e2 = fd3(2 + dw);
        dcl2 = e0; dch2 = e2; cdup2 = (e2 != e0);
        csel2[0] = false; csel2[1] = (e1 != e0); csel2[2] = (e2 != e0);
    }
    const bool vneed0 = (rv[0][1] != rv[0][0]);
    const bool vneed2 = (rv[2][1] != rv[2][0]);
    const float4 bias4 = *(const float4*)&bias[co0];
    float4 lsum4 = make_float4(0.f, 0.f, 0.f, 0.f);
    float4 lsq4  = make_float4(0.f, 0.f, 0.f, 0.f);

#pragma unroll
    for (int j = 0; j < 2; j++) {
        int pix = tid + (j << 9), py = pix >> 5, px = pix & 31;
        const int colA0 = 4 + px + dcl0, colB0 = 4 + px + dch0;
        const int colC  = 4 + px;
        const int colA2 = 4 + px + dcl2, colB2 = 4 + px + dch2;

        float4 RS1[3];
        {
            int r3 = (3 * 33 + py) * 40, r4 = r3 + 1320, r5 = r4 + 1320;
            float4 A0 = Y4[r3 + colA0];
            float4 B0 = cdup0 ? Y4[r3 + colB0] : A0;
            float4 Lc = Y4[r4 + colC];
            float4 A2 = Y4[r5 + colA2];
            float4 B2 = cdup2 ? Y4[r5 + colB2] : A2;
#pragma unroll
            for (int s = 0; s < 3; s++)
                RS1[s] = f4add(Lc,
                          f4add(f4sel(csel0[s], B0, A0), f4sel(csel2[s], B2, A2)));
        }
        float4 RS0[2][3], RS2[2][3];
#pragma unroll
        for (int ki = 0; ki < 3; ki += 2) {
            float4 (*RS)[3] = (ki == 0) ? RS0 : RS2;
            const bool vneed = (ki == 0) ? vneed0 : vneed2;
#pragma unroll
            for (int v = 0; v < 2; v++) {
                if (v == 1 && !vneed) {
#pragma unroll
                    for (int s = 0; s < 3; s++) RS[1][s] = RS[0][s];
                    break;
                }
                int row = py + rv[ki][v];
                int rowsel = ((unsigned)row < 32u) ? row : ZROW;
                int t0 = ((ki * 3) * 33 + rowsel) * 40, t1 = t0 + 1320, t2 = t1 + 1320;
                float4 A0 = Y4[t0 + colA0];
                float4 B0 = cdup0 ? Y4[t0 + colB0] : A0;
                float4 Lc = Y4[t1 + colC];
                float4 A2 = Y4[t2 + colA2];
                float4 B2 = cdup2 ? Y4[t2 + colB2] : A2;
#pragma unroll
                for (int s = 0; s < 3; s++)
                    RS[v][s] = f4add(Lc,
                        f4add(f4sel(csel0[s], B0, A0), f4sel(csel2[s], B2, A2)));
            }
        }
        float4 mall = make_float4(-INFINITY, -INFINITY, -INFINITY, -INFINITY);
#pragma unroll
        for (int s = 0; s < 3; s++) {
            float4 t0 = f4add(RS0[0][s], RS2[0][s]);
            float4 t1 = f4add(rsel[0][1] ? RS0[1][s] : RS0[0][s],
                              rsel[2][1] ? RS2[1][s] : RS2[0][s]);
            float4 t2 = f4add(rsel[0][2] ? RS0[1][s] : RS0[0][s],
                              rsel[2][2] ? RS2[1][s] : RS2[0][s]);
            float4 u = f4max(t0, f4max(t1, t2));
            mall = f4max(mall, f4add(u, RS1[s]));
        }
        float4 mx = f4add(bias4, mall);
        float* ob = out + ((size_t)b * COUTT + co0) * NPIX + pix;
        ob[0]        = mx.x;
        ob[NPIX]     = mx.y;
        ob[2 * NPIX] = mx.z;
        ob[3 * NPIX] = mx.w;
        lsum4 = f4add(lsum4, mx);
        lsq4.x += mx.x * mx.x; lsq4.y += mx.y * mx.y;
        lsq4.z += mx.z * mx.z; lsq4.w += mx.w * mx.w;
    }
#pragma unroll
    for (int o = 16; o > 0; o >>= 1) {
        lsum4.x += __shfl_xor_sync(0xFFFFFFFFu, lsum4.x, o);
        lsum4.y += __shfl_xor_sync(0xFFFFFFFFu, lsum4.y, o);
        lsum4.z += __shfl_xor_sync(0xFFFFFFFFu, lsum4.z, o);
        lsum4.w += __shfl_xor_sync(0xFFFFFFFFu, lsum4.w, o);
        lsq4.x  += __shfl_xor_sync(0xFFFFFFFFu, lsq4.x, o);
        lsq4.y  += __shfl_xor_sync(0xFFFFFFFFu, lsq4.y, o);
        lsq4.z  += __shfl_xor_sync(0xFFFFFFFFu, lsq4.z, o);
        lsq4.w  += __shfl_xor_sync(0xFFFFFFFFu, lsq4.w, o);
    }
    __syncthreads();
    if (l == 0) {
        float* rw = red + wid * 8;
        rw[0] = lsum4.x; rw[1] = lsq4.x;
        rw[2] = lsum4.y; rw[3] = lsq4.y;
        rw[4] = lsum4.z; rw[5] = lsq4.z;
        rw[6] = lsum4.w; rw[7] = lsq4.w;
    }
    __syncthreads();
    if (tid < TC) {
        float s = 0.f, q = 0.f;
#pragma unroll
        for (int wdx = 0; wdx < 16; wdx++) {
            s += red[wdx * 8 + tid * 2];
            q += red[wdx * 8 + tid * 2 + 1];
        }
        g_psum[(co0 + tid) * BB + b] = s;
        g_psumsq[(co0 + tid) * BB + b] = q;
    }
}

// warp-per-channel: grid 4 x 1024 threads = 128 warps
__global__ void __launch_bounds__(1024)
stats_kernel(const float* __restrict__ gamma, const float* __restrict__ beta)
{
    int gw = (blockIdx.x * 1024 + threadIdx.x) >> 5;   // channel 0..127
    int l = threadIdx.x & 31;
    float s = g_psum[gw * BB + l] + g_psum[gw * BB + 32 + l];
    float q = g_psumsq[gw * BB + l] + g_psumsq[gw * BB + 32 + l];
#pragma unroll
    for (int o = 16; o > 0; o >>= 1) {
        s += __shfl_xor_sync(0xFFFFFFFFu, s, o);
        q += __shfl_xor_sync(0xFFFFFFFFu, q, o);
    }
    if (l == 0) {
        const float inv = 1.0f / 65536.0f;
        float mean = s * inv, var = q * inv - mean * mean;
        float sc = gamma[gw] * rsqrtf(var + 1e-5f);
        g_scale[gw] = sc;
        g_shift[gw] = beta[gw] - mean * sc;
    }
}

__global__ void __launch_bounds__(1024)
apply_kernel(float* __restrict__ out)
{
    int i = blockIdx.x * 1024 + threadIdx.x;   // grid 2048, one float4 per thread
    int c = (i >> 8) & 127;
    float4 v = ((float4*)out)[i];
    float sc = g_scale[c], sh = g_shift[c];
    v.x = fmaxf(fmaf(v.x, sc, sh), 0.f);
    v.y = fmaxf(fmaf(v.y, sc, sh), 0.f);
    v.z = fmaxf(fmaf(v.z, sc, sh), 0.f);
    v.w = fmaxf(fmaf(v.w, sc, sh), 0.f);
    ((float4*)out)[i] = v;
}

extern "C" void kernel_launch(void* const* d_in, const int* in_sizes, int n_in,
                              void* d_out, int out_size)
{
    const float* x      = (const float*)d_in[0];
    const int*   h      = (const int*)  d_in[1];
    const int*   w      = (const int*)  d_in[2];
    const float* weight = (const float*)d_in[3];
    const float* bias   = (const float*)d_in[4];
    const float* gamma  = (const float*)d_in[5];
    const float* beta   = (const float*)d_in[6];
    float* out = (float*)d_out;

    cudaFuncSetAttribute(build_A, cudaFuncAttributeMaxDynamicSharedMemorySize, 66048);
    cudaFuncSetAttribute(fused_kernel, cudaFuncAttributeMaxDynamicSharedMemorySize, SMEM_TOTAL);

    build_A<<<dim3(4, BB), 512, 66048>>>(x);
    fused_kernel<<<dim3(COUTT / TC, BB), 512, SMEM_TOTAL>>>(h, w, weight, bias, out);
    stats_kernel<<<4, 1024>>>(gamma, beta);
    apply_kernel<<<2048, 1024>>>(out);
}